// round 15
// baseline (speedup 1.0000x reference)
#include <cuda_runtime.h>

#define GRIDSZ 32
#define BATCH  16
#define NPTS   131072
#define GCELLS 32768
#define TPB    1024
#define REPL   9                      // 9 x 16 = 144 CTAs, 1 per SM
#define STRIDE (REPL * TPB)           // 9216
#define TAILPT (3 * STRIDE * 4)       // 110592: first tail point
#define THR3   2048                   // threads that take a 3rd tail point

#define SMEM_BYTES (GCELLS * 4)       // 128KB packed table

#define ENC8      8.0f                // 0.125-step quantization (exact consts)
#define MAGIC     8388608.0f          // 2^23
#define IDXSCALE  31.99999809f        // largest float < 32
#define INV256    0.00390625f
#define FLBIAS    (0x4B000000u * 1057u)   // (1024+32+1)*0x4B000000 mod 2^32

__device__ __forceinline__ float fma_rz(float a, float b, float c) {
    float r;
    asm("fma.rz.f32 %0, %1, %2, %3;" : "=f"(r) : "f"(a), "f"(b), "f"(c));
    return r;
}
__device__ __forceinline__ float fma_sat(float a, float b, float c) {
    float r;
    asm("fma.rn.sat.f32 %0, %1, %2, %3;" : "=f"(r) : "f"(a), "f"(b), "f"(c));
    return r;
}

// process NP points against all 6 transforms (biased 8x space), two accs
template <int NP>
__device__ __forceinline__ void process_pts(
    const float* PX, const float* PY, const float* PZ,
    const float4* __restrict__ sc4,
    const unsigned int* __restrict__ s_tab,
    float& acc0, float& acc1)
{
#pragma unroll
    for (int j = 0; j < 6; j++) {
        const float4 r0 = sc4[j * 3 + 0];
        const float4 r1 = sc4[j * 3 + 1];
        const float4 r2 = sc4[j * 3 + 2];

        float sx[NP], sy[NP], sz[NP];
        unsigned fl[NP];
#pragma unroll
        for (int p = 0; p < NP; p++) {
            // biased-scaled transform: s8 = 8*M*p + (2^23 + 8t)
            sx[p] = fmaf(r0.x, PX[p], fmaf(r0.y, PY[p], fmaf(r0.z, PZ[p], r0.w)));
            sy[p] = fmaf(r1.x, PX[p], fmaf(r1.y, PY[p], fmaf(r1.z, PZ[p], r1.w)));
            sz[p] = fmaf(r2.x, PX[p], fmaf(r2.y, PY[p], fmaf(r2.z, PZ[p], r2.w)));
            // index: n = sat((s8 - 2^23)/256)  (exact arithmetic)
            float nx = fma_sat(sx[p], INV256, -32768.0f);
            float ny = fma_sat(sy[p], INV256, -32768.0f);
            float nz = fma_sat(sz[p], INV256, -32768.0f);
            unsigned bx = __float_as_uint(fma_rz(nx, IDXSCALE, MAGIC));
            unsigned by = __float_as_uint(fma_rz(ny, IDXSCALE, MAGIC));
            unsigned bz = __float_as_uint(fma_rz(nz, IDXSCALE, MAGIC));
            unsigned bzs = bz ^ ((bx ^ by) & 31u);   // bank scramble
            fl[p] = bx * 1024u + by * 32u + bzs - FLBIAS;
        }

        unsigned u[NP];
#pragma unroll
        for (int p = 0; p < NP; p++) u[p] = s_tab[fl[p]];

        float& acc = (j & 1) ? acc1 : acc0;
#pragma unroll
        for (int p = 0; p < NP; p++) {
            // PRMT decode -> float bits [q,0,0,0x4B] = 2^23 + q
            float cxf = __uint_as_float(__byte_perm(u[p], 0x4B000000u, 0x7543));
            float cyf = __uint_as_float(__byte_perm(u[p], 0x4B000000u, 0x7542));
            float czf = __uint_as_float(__byte_perm(u[p], 0x4B000000u, 0x7541));
            float dx = cxf - sx[p];          // exact: q - round(8s)
            float dy = cyf - sy[p];
            float dz = czf - sz[p];
            float d2 = fmaf(dx, dx, fmaf(dy, dy, fmaf(dz, dz, 1e-30f)));
            acc = fmaf(d2, rsqrtf(d2), acc);
        }
    }
}

__device__ __forceinline__ void process_chunk(
    float4 f0, float4 f1, float4 f2,
    const float4* __restrict__ sc4,
    const unsigned int* __restrict__ s_tab,
    float& acc0, float& acc1)
{
    const float PX[4] = {f0.x, f0.w, f1.z, f2.y};
    const float PY[4] = {f0.y, f1.x, f1.w, f2.z};
    const float PZ[4] = {f0.z, f1.y, f2.x, f2.w};
    process_pts<4>(PX, PY, PZ, sc4, s_tab, acc0, acc1);
}

__global__ void __launch_bounds__(TPB, 1)
sym_loss_kernel(const float* __restrict__ points,
                const float* __restrict__ closest,
                const float* __restrict__ out6,
                float* __restrict__ d_out) {
    extern __shared__ unsigned int s_tab[];   // 128KB packed 8:8:8 table
    __shared__ float4 sc4[18];
    __shared__ float wsum[TPB / 32];

    const int b   = blockIdx.y;
    const int r   = blockIdx.x;
    const int tid = threadIdx.x;

    // ---- constants: rows of 8*M, addend w = 2^23 + 8*t
    if (tid < 6) {
        const float* q = out6 + (b * 6 + tid) * 4;
        float q0 = q[0], q1 = q[1], q2 = q[2], q3 = q[3];
        float m[9], t0, t1, t2;
        if (tid < 3) {
            // reflection: p' = (I - a n^T) p - d a,  a = 2n/|n|^2
            float inv = 1.0f / (q0 * q0 + q1 * q1 + q2 * q2);
            float a0 = 2.0f * q0 * inv, a1 = 2.0f * q1 * inv, a2 = 2.0f * q2 * inv;
            m[0] = 1.0f - a0 * q0; m[1] =       -a0 * q1; m[2] =       -a0 * q2;
            m[3] =       -a1 * q0; m[4] = 1.0f - a1 * q1; m[5] =       -a1 * q2;
            m[6] =       -a2 * q0; m[7] =       -a2 * q1; m[8] = 1.0f - a2 * q2;
            t0 = -q3 * a0; t1 = -q3 * a1; t2 = -q3 * a2;
        } else {
            // rotation: (q p q~)/||q|| (reference _qinv normalizes by ||q|| once)
            float w = q0, x = q1, y = q2, z = q3;
            float vv = x * x + y * y + z * z;
            float s = rsqrtf(w * w + vv);
            float ww = w * w - vv;
            m[0] = s * (ww + 2.0f * x * x);
            m[1] = s * 2.0f * (x * y - w * z);
            m[2] = s * 2.0f * (x * z + w * y);
            m[3] = s * 2.0f * (x * y + w * z);
            m[4] = s * (ww + 2.0f * y * y);
            m[5] = s * 2.0f * (y * z - w * x);
            m[6] = s * 2.0f * (x * z - w * y);
            m[7] = s * 2.0f * (y * z + w * x);
            m[8] = s * (ww + 2.0f * z * z);
            t0 = t1 = t2 = 0.0f;
        }
        sc4[tid * 3 + 0] = make_float4(8.0f*m[0], 8.0f*m[1], 8.0f*m[2], MAGIC + 8.0f*t0);
        sc4[tid * 3 + 1] = make_float4(8.0f*m[3], 8.0f*m[4], 8.0f*m[5], MAGIC + 8.0f*t1);
        sc4[tid * 3 + 2] = make_float4(8.0f*m[6], 8.0f*m[7], 8.0f*m[8], MAGIC + 8.0f*t2);
    }

    // ---- sync-free table build: 8:8:8 (scale 8) bytes 3,2,1; scrambled slots
    {
        const float4* __restrict__ cb4 =
            (const float4*)(closest + (size_t)b * GCELLS * 3);
#pragma unroll
        for (int it = 0; it < GCELLS / (4 * TPB); it++) {   // 8 iterations
            int g = it * TPB + tid;
            float4 a = cb4[3 * g + 0];
            float4 c = cb4[3 * g + 1];
            float4 e = cb4[3 * g + 2];
            float X[4] = {a.x, a.w, c.z, e.y};
            float Y[4] = {a.y, c.x, c.w, e.z};
            float Z[4] = {a.z, c.y, e.x, e.w};
#pragma unroll
            for (int k = 0; k < 4; k++) {
                unsigned qx = min(255, (int)fmaf(X[k], ENC8, 0.5f));
                unsigned qy = min(255, (int)fmaf(Y[k], ENC8, 0.5f));
                unsigned qz = min(255, (int)fmaf(Z[k], ENC8, 0.5f));
                unsigned cell = 4 * g + k;            // (ix<<10)|(iy<<5)|iz
                unsigned ix = cell >> 10;
                unsigned iy = (cell >> 5) & 31;
                unsigned slot = (cell & ~31u) | ((cell ^ ix ^ iy) & 31u);
                s_tab[slot] = (qx << 24) | (qy << 16) | (qz << 8);
            }
        }
    }
    __syncthreads();

    // ---- main: fixed 3 chunks/thread with register prefetch
    const float4* __restrict__ pb4 =
        (const float4*)(points + (size_t)b * NPTS * 3);
    const float* __restrict__ pbf = points + (size_t)b * NPTS * 3;
    float acc0 = 0.0f, acc1 = 0.0f;

    const int c0 = r * TPB + tid;
    float4 f0 = __ldg(&pb4[3 * c0 + 0]);
    float4 f1 = __ldg(&pb4[3 * c0 + 1]);
    float4 f2 = __ldg(&pb4[3 * c0 + 2]);

#pragma unroll
    for (int k = 0; k < 3; k++) {
        float4 g0, g1, g2;
        if (k < 2) {                      // static prefetch (always in range)
            const int cn = c0 + (k + 1) * STRIDE;
            g0 = __ldg(&pb4[3 * cn + 0]);
            g1 = __ldg(&pb4[3 * cn + 1]);
            g2 = __ldg(&pb4[3 * cn + 2]);
        }
        process_chunk(f0, f1, f2, sc4, s_tab, acc0, acc1);
        f0 = g0; f1 = g1; f2 = g2;
    }

    // ---- tail: 20480 points, 1-pt granularity, single pass per thread.
    // thread t gets points TAILPT+t, TAILPT+STRIDE+t, and (t<2048) +2*STRIDE+t.
    // 2048 % 32 == 0 -> branch is warp-uniform.
    {
        const int t  = r * TPB + tid;
        const int i0 = TAILPT + t;
        const int i1 = i0 + STRIDE;

        if (t < THR3) {
            const int i2 = i1 + STRIDE;          // max 131071 < NPTS
            float PX[3], PY[3], PZ[3];
            PX[0] = __ldg(&pbf[3 * i0 + 0]);
            PY[0] = __ldg(&pbf[3 * i0 + 1]);
            PZ[0] = __ldg(&pbf[3 * i0 + 2]);
            PX[1] = __ldg(&pbf[3 * i1 + 0]);
            PY[1] = __ldg(&pbf[3 * i1 + 1]);
            PZ[1] = __ldg(&pbf[3 * i1 + 2]);
            PX[2] = __ldg(&pbf[3 * i2 + 0]);
            PY[2] = __ldg(&pbf[3 * i2 + 1]);
            PZ[2] = __ldg(&pbf[3 * i2 + 2]);
            process_pts<3>(PX, PY, PZ, sc4, s_tab, acc0, acc1);
        } else {
            float PX[2], PY[2], PZ[2];
            PX[0] = __ldg(&pbf[3 * i0 + 0]);
            PY[0] = __ldg(&pbf[3 * i0 + 1]);
            PZ[0] = __ldg(&pbf[3 * i0 + 2]);
            PX[1] = __ldg(&pbf[3 * i1 + 0]);
            PY[1] = __ldg(&pbf[3 * i1 + 1]);
            PZ[1] = __ldg(&pbf[3 * i1 + 2]);
            process_pts<2>(PX, PY, PZ, sc4, s_tab, acc0, acc1);
        }
    }

    // ---- reduce (distances in 8x-scaled space -> multiply by 0.125)
    float acc = acc0 + acc1;
#pragma unroll
    for (int o = 16; o > 0; o >>= 1)
        acc += __shfl_down_sync(0xffffffffu, acc, o);
    if ((tid & 31) == 0) wsum[tid >> 5] = acc;
    __syncthreads();
    if (tid == 0) {
        float s = 0.0f;
#pragma unroll
        for (int w = 0; w < TPB / 32; w++) s += wsum[w];
        atomicAdd(d_out, s * (0.125f / BATCH));
    }
}

// ---------------------------------------------------------------------------
extern "C" void kernel_launch(void* const* d_in, const int* in_sizes, int n_in,
                              void* d_out, int out_size) {
    const float* output  = nullptr;
    const float* points  = nullptr;
    const float* closest = nullptr;
    for (int i = 0; i < n_in; i++) {
        if (in_sizes[i] == BATCH * 6 * 4)           output  = (const float*)d_in[i];
        else if (in_sizes[i] == BATCH * NPTS * 3)   points  = (const float*)d_in[i];
        else if (in_sizes[i] == BATCH * GCELLS * 3) closest = (const float*)d_in[i];
    }

    cudaFuncSetAttribute(sym_loss_kernel,
                         cudaFuncAttributeMaxDynamicSharedMemorySize,
                         (int)SMEM_BYTES);

    cudaMemsetAsync(d_out, 0, sizeof(float));

    dim3 grid(REPL, BATCH);
    sym_loss_kernel<<<grid, TPB, SMEM_BYTES>>>(points, closest, output,
                                               (float*)d_out);
}

// round 16
// speedup vs baseline: 1.3153x; 1.3153x over previous
#include <cuda_runtime.h>

#define GRIDSZ 32
#define BATCH  16
#define NPTS   131072
#define GCELLS 32768
#define TPB    1024
#define REPL   9                      // 9 x 16 = 144 CTAs, 1 per SM
#define NCHUNK (NPTS / 4)             // 32768 four-point chunks per batch
#define STRIDE (REPL * TPB)           // 9216
#define TAILBASE (3 * STRIDE)         // 27648
#define TAILCNT  (NCHUNK - TAILBASE)  // 5120
#define TAILPER  569                  // ceil(5120/9)

#define SMEM_BYTES (GCELLS * 4)       // 128KB packed table

#define ENC8      8.0f                // 0.125-step quantization (exact consts)
#define MAGIC     8388608.0f          // 2^23
#define IDXSCALE  31.99999809f        // largest float < 32
#define INV256    0.00390625f
#define FLBIAS    (0x4B000000u * 1057u)   // (1024+32+1)*0x4B000000 mod 2^32

__device__ __forceinline__ float fma_rz(float a, float b, float c) {
    float r;
    asm("fma.rz.f32 %0, %1, %2, %3;" : "=f"(r) : "f"(a), "f"(b), "f"(c));
    return r;
}
__device__ __forceinline__ float fma_sat(float a, float b, float c) {
    float r;
    asm("fma.rn.sat.f32 %0, %1, %2, %3;" : "=f"(r) : "f"(a), "f"(b), "f"(c));
    return r;
}

// process one 4-point chunk against all 6 transforms (biased 8x space)
__device__ __forceinline__ void process_chunk(
    float4 f0, float4 f1, float4 f2,
    const float4* __restrict__ sc4,
    const unsigned int* __restrict__ s_tab,
    float& acc0, float& acc1)
{
    const float PX[4] = {f0.x, f0.w, f1.z, f2.y};
    const float PY[4] = {f0.y, f1.x, f1.w, f2.z};
    const float PZ[4] = {f0.z, f1.y, f2.x, f2.w};

#pragma unroll
    for (int j = 0; j < 6; j++) {
        const float4 r0 = sc4[j * 3 + 0];
        const float4 r1 = sc4[j * 3 + 1];
        const float4 r2 = sc4[j * 3 + 2];

        float sx[4], sy[4], sz[4];
        unsigned fl[4];
#pragma unroll
        for (int p = 0; p < 4; p++) {
            // biased-scaled transform: s8 = 8*M*p + (2^23 + 8t)
            sx[p] = fmaf(r0.x, PX[p], fmaf(r0.y, PY[p], fmaf(r0.z, PZ[p], r0.w)));
            sy[p] = fmaf(r1.x, PX[p], fmaf(r1.y, PY[p], fmaf(r1.z, PZ[p], r1.w)));
            sz[p] = fmaf(r2.x, PX[p], fmaf(r2.y, PY[p], fmaf(r2.z, PZ[p], r2.w)));
            // index: n = sat((s8 - 2^23)/256)  (exact arithmetic)
            float nx = fma_sat(sx[p], INV256, -32768.0f);
            float ny = fma_sat(sy[p], INV256, -32768.0f);
            float nz = fma_sat(sz[p], INV256, -32768.0f);
            unsigned bx = __float_as_uint(fma_rz(nx, IDXSCALE, MAGIC));
            unsigned by = __float_as_uint(fma_rz(ny, IDXSCALE, MAGIC));
            unsigned bz = __float_as_uint(fma_rz(nz, IDXSCALE, MAGIC));
            unsigned bzs = bz ^ ((bx ^ by) & 31u);   // bank scramble
            fl[p] = bx * 1024u + by * 32u + bzs - FLBIAS;
        }

        unsigned u[4];
#pragma unroll
        for (int p = 0; p < 4; p++) u[p] = s_tab[fl[p]];

        float& acc = (j & 1) ? acc1 : acc0;
#pragma unroll
        for (int p = 0; p < 4; p++) {
            // PRMT decode -> float bits [q,0,0,0x4B] = 2^23 + q
            float cxf = __uint_as_float(__byte_perm(u[p], 0x4B000000u, 0x7543));
            float cyf = __uint_as_float(__byte_perm(u[p], 0x4B000000u, 0x7542));
            float czf = __uint_as_float(__byte_perm(u[p], 0x4B000000u, 0x7541));
            float dx = cxf - sx[p];          // exact: q - round(8s)
            float dy = cyf - sy[p];
            float dz = czf - sz[p];
            float d2 = fmaf(dx, dx, fmaf(dy, dy, fmaf(dz, dz, 1e-30f)));
            acc = fmaf(d2, rsqrtf(d2), acc);
        }
    }
}

__global__ void __launch_bounds__(TPB, 1)
sym_loss_kernel(const float* __restrict__ points,
                const float* __restrict__ closest,
                const float* __restrict__ out6,
                float* __restrict__ d_out) {
    extern __shared__ unsigned int s_tab[];   // 128KB packed 8:8:8 table
    __shared__ float4 sc4[18];
    __shared__ float wsum[TPB / 32];

    const int b   = blockIdx.y;
    const int r   = blockIdx.x;
    const int tid = threadIdx.x;

    // ---- constants: rows of 8*M, addend w = 2^23 + 8*t
    if (tid < 6) {
        const float* q = out6 + (b * 6 + tid) * 4;
        float q0 = q[0], q1 = q[1], q2 = q[2], q3 = q[3];
        float m[9], t0, t1, t2;
        if (tid < 3) {
            // reflection: p' = (I - a n^T) p - d a,  a = 2n/|n|^2
            float inv = 1.0f / (q0 * q0 + q1 * q1 + q2 * q2);
            float a0 = 2.0f * q0 * inv, a1 = 2.0f * q1 * inv, a2 = 2.0f * q2 * inv;
            m[0] = 1.0f - a0 * q0; m[1] =       -a0 * q1; m[2] =       -a0 * q2;
            m[3] =       -a1 * q0; m[4] = 1.0f - a1 * q1; m[5] =       -a1 * q2;
            m[6] =       -a2 * q0; m[7] =       -a2 * q1; m[8] = 1.0f - a2 * q2;
            t0 = -q3 * a0; t1 = -q3 * a1; t2 = -q3 * a2;
        } else {
            // rotation: (q p q~)/||q|| (reference _qinv normalizes by ||q|| once)
            float w = q0, x = q1, y = q2, z = q3;
            float vv = x * x + y * y + z * z;
            float s = rsqrtf(w * w + vv);
            float ww = w * w - vv;
            m[0] = s * (ww + 2.0f * x * x);
            m[1] = s * 2.0f * (x * y - w * z);
            m[2] = s * 2.0f * (x * z + w * y);
            m[3] = s * 2.0f * (x * y + w * z);
            m[4] = s * (ww + 2.0f * y * y);
            m[5] = s * 2.0f * (y * z - w * x);
            m[6] = s * 2.0f * (x * z - w * y);
            m[7] = s * 2.0f * (y * z + w * x);
            m[8] = s * (ww + 2.0f * z * z);
            t0 = t1 = t2 = 0.0f;
        }
        sc4[tid * 3 + 0] = make_float4(8.0f*m[0], 8.0f*m[1], 8.0f*m[2], MAGIC + 8.0f*t0);
        sc4[tid * 3 + 1] = make_float4(8.0f*m[3], 8.0f*m[4], 8.0f*m[5], MAGIC + 8.0f*t1);
        sc4[tid * 3 + 2] = make_float4(8.0f*m[6], 8.0f*m[7], 8.0f*m[8], MAGIC + 8.0f*t2);
    }

    // ---- sync-free table build: 8:8:8 (scale 8) bytes 3,2,1; scrambled slots
    {
        const float4* __restrict__ cb4 =
            (const float4*)(closest + (size_t)b * GCELLS * 3);
#pragma unroll
        for (int it = 0; it < GCELLS / (4 * TPB); it++) {   // 8 iterations
            int g = it * TPB + tid;
            float4 a = cb4[3 * g + 0];
            float4 c = cb4[3 * g + 1];
            float4 e = cb4[3 * g + 2];
            float X[4] = {a.x, a.w, c.z, e.y};
            float Y[4] = {a.y, c.x, c.w, e.z};
            float Z[4] = {a.z, c.y, e.x, e.w};
#pragma unroll
            for (int k = 0; k < 4; k++) {
                unsigned qx = min(255, (int)fmaf(X[k], ENC8, 0.5f));
                unsigned qy = min(255, (int)fmaf(Y[k], ENC8, 0.5f));
                unsigned qz = min(255, (int)fmaf(Z[k], ENC8, 0.5f));
                unsigned cell = 4 * g + k;            // (ix<<10)|(iy<<5)|iz
                unsigned ix = cell >> 10;
                unsigned iy = (cell >> 5) & 31;
                unsigned slot = (cell & ~31u) | ((cell ^ ix ^ iy) & 31u);
                s_tab[slot] = (qx << 24) | (qy << 16) | (qz << 8);
            }
        }
    }
    __syncthreads();

    // ---- main: 3 chunks/thread, ROLLED loop (single code copy) + prefetch
    const float4* __restrict__ pb4 =
        (const float4*)(points + (size_t)b * NPTS * 3);
    float acc0 = 0.0f, acc1 = 0.0f;

    const int c0 = r * TPB + tid;
    float4 f0 = __ldg(&pb4[3 * c0 + 0]);
    float4 f1 = __ldg(&pb4[3 * c0 + 1]);
    float4 f2 = __ldg(&pb4[3 * c0 + 2]);

#pragma unroll 1
    for (int k = 0; k < 3; k++) {
        float4 g0, g1, g2;
        if (k < 2) {                      // predicated prefetch (in range)
            const int cn = c0 + (k + 1) * STRIDE;
            g0 = __ldg(&pb4[3 * cn + 0]);
            g1 = __ldg(&pb4[3 * cn + 1]);
            g2 = __ldg(&pb4[3 * cn + 2]);
        }
        process_chunk(f0, f1, f2, sc4, s_tab, acc0, acc1);
        f0 = g0; f1 = g1; f2 = g2;
    }

    // tail: 5120 remaining chunks spread over all 9 replicas (569 each)
    {
        const int idx = r * TAILPER + tid;
        if (tid < TAILPER && idx < TAILCNT) {
            const int ct = TAILBASE + idx;
            float4 t0 = __ldg(&pb4[3 * ct + 0]);
            float4 t1 = __ldg(&pb4[3 * ct + 1]);
            float4 t2 = __ldg(&pb4[3 * ct + 2]);
            process_chunk(t0, t1, t2, sc4, s_tab, acc0, acc1);
        }
    }

    // ---- reduce (distances in 8x-scaled space -> multiply by 0.125)
    float acc = acc0 + acc1;
#pragma unroll
    for (int o = 16; o > 0; o >>= 1)
        acc += __shfl_down_sync(0xffffffffu, acc, o);
    if ((tid & 31) == 0) wsum[tid >> 5] = acc;
    __syncthreads();
    if (tid == 0) {
        float s = 0.0f;
#pragma unroll
        for (int w = 0; w < TPB / 32; w++) s += wsum[w];
        atomicAdd(d_out, s * (0.125f / BATCH));
    }
}

// ---------------------------------------------------------------------------
extern "C" void kernel_launch(void* const* d_in, const int* in_sizes, int n_in,
                              void* d_out, int out_size) {
    const float* output  = nullptr;
    const float* points  = nullptr;
    const float* closest = nullptr;
    for (int i = 0; i < n_in; i++) {
        if (in_sizes[i] == BATCH * 6 * 4)           output  = (const float*)d_in[i];
        else if (in_sizes[i] == BATCH * NPTS * 3)   points  = (const float*)d_in[i];
        else if (in_sizes[i] == BATCH * GCELLS * 3) closest = (const float*)d_in[i];
    }

    cudaFuncSetAttribute(sym_loss_kernel,
                         cudaFuncAttributeMaxDynamicSharedMemorySize,
                         (int)SMEM_BYTES);

    cudaMemsetAsync(d_out, 0, sizeof(float));

    dim3 grid(REPL, BATCH);
    sym_loss_kernel<<<grid, TPB, SMEM_BYTES>>>(points, closest, output,
                                               (float*)d_out);
}